// round 3
// baseline (speedup 1.0000x reference)
#include <cuda_runtime.h>
#include <cstdint>

#define B_  16
#define NC_ 10
#define H_  6
#define C_  384
#define HD_ 64
#define T_  197
#define N_  196
#define BH_ (B_*H_)    // 96
#define CH_ (NC_*H_)   // 60
#define SCALE_ 0.125f

// ---------------- scratch ----------------
__device__ float g_n1 [26*C_];
__device__ float g_n2x[B_*N_*C_];
__device__ float g_n2a[NC_*N_*C_];
__device__ float g_qv [NC_*2*C_];
__device__ float g_k  [B_*C_];
__device__ float g_attn[B_*CH_];
__device__ float g_ctx[B_*C_];
__device__ float g_qh [BH_*N_*HD_];
__device__ float g_q2 [BH_*N_*HD_];
__device__ float g_vr [BH_*N_*HD_];
__device__ float g_kh [CH_*N_*HD_];
__device__ float g_k2 [CH_*N_*HD_];
__device__ float g_tmp[BH_*N_*N_];
__device__ float g_rectH[B_*N_*C_];
__device__ float g_xx [B_*T_*C_];
__device__ float g_hdn[B_*T_*C_];
__device__ float g_h1 [B_*T_*4*C_];

// ---------------- helpers ----------------
__device__ __forceinline__ float to_tf32(float x) {
    uint32_t u;
    asm("cvt.rna.tf32.f32 %0, %1;" : "=r"(u) : "f"(x));
    return __uint_as_float(u);
}
#define U32(x) __float_as_uint(x)

__device__ __forceinline__ void mma8(float* c, uint32_t a0, uint32_t a1, uint32_t a2, uint32_t a3,
                                     uint32_t b0, uint32_t b1)
{
    asm volatile("mma.sync.aligned.m16n8k8.row.col.f32.tf32.tf32.f32 "
                 "{%0,%1,%2,%3},{%4,%5,%6,%7},{%8,%9},{%0,%1,%2,%3};\n"
                 : "+f"(c[0]), "+f"(c[1]), "+f"(c[2]), "+f"(c[3])
                 : "r"(a0), "r"(a1), "r"(a2), "r"(a3), "r"(b0), "r"(b1));
}

__device__ __forceinline__ float gelu_f(float x) {
    return 0.5f * x * (1.f + erff(x * 0.7071067811865475f));
}

// ---------------- LayerNorm ----------------
__global__ void ln_kernel(const float* __restrict__ in, float* __restrict__ out,
                          const float* __restrict__ g, const float* __restrict__ bt,
                          int rows, int inner, long outer_stride, long inner_stride)
{
    int row = blockIdx.x;
    if (row >= rows) return;
    const float* src = in + (long)(row / inner) * outer_stride + (long)(row % inner) * inner_stride;
    int t = threadIdx.x;
    float v[3]; float s = 0.f;
#pragma unroll
    for (int i = 0; i < 3; i++) { v[i] = src[t + i*128]; s += v[i]; }
    __shared__ float red[4];
#pragma unroll
    for (int o = 16; o > 0; o >>= 1) s += __shfl_xor_sync(0xffffffffu, s, o);
    if ((t & 31) == 0) red[t >> 5] = s;
    __syncthreads();
    float mean = (red[0] + red[1] + red[2] + red[3]) * (1.f/384.f);
    float q = 0.f;
#pragma unroll
    for (int i = 0; i < 3; i++) { float d = v[i] - mean; q += d*d; }
#pragma unroll
    for (int o = 16; o > 0; o >>= 1) q += __shfl_xor_sync(0xffffffffu, q, o);
    __syncthreads();
    if ((t & 31) == 0) red[t >> 5] = q;
    __syncthreads();
    float var = (red[0] + red[1] + red[2] + red[3]) * (1.f/384.f);
    float rs = rsqrtf(var + 1e-5f);
    float* dst = out + (long)row * C_;
#pragma unroll
    for (int i = 0; i < 3; i++) { int c = t + i*128; dst[c] = (v[i] - mean) * rs * g[c] + bt[c]; }
}

// ---------------- cls attention ----------------
__global__ void attn_cls_kernel(const float* __restrict__ qv, const float* __restrict__ k,
                                float* __restrict__ attn, float* __restrict__ ctx)
{
    int b = blockIdx.x, t = threadIdx.x; // 384 threads
    __shared__ float sl[CH_];
    if (t < CH_) {
        int n = t / H_, h = t % H_;
        float s = 0.f;
        for (int d = 0; d < HD_; d++) s += qv[n*2*C_ + h*HD_ + d] * k[b*C_ + h*HD_ + d];
        sl[t] = s * SCALE_;
    }
    __syncthreads();
    if (t < H_) {
        float mx = -1e30f;
        for (int n = 0; n < NC_; n++) mx = fmaxf(mx, sl[n*H_ + t]);
        float sum = 0.f;
        for (int n = 0; n < NC_; n++) { float e = expf(sl[n*H_ + t] - mx); sl[n*H_ + t] = e; sum += e; }
        float inv = 1.f / sum;
        for (int n = 0; n < NC_; n++) { sl[n*H_ + t] *= inv; attn[b*CH_ + n*H_ + t] = sl[n*H_ + t]; }
    }
    __syncthreads();
    {
        int h = t >> 6, d = t & 63;
        float s = 0.f;
        for (int n = 0; n < NC_; n++) s += sl[n*H_ + h] * qv[n*2*C_ + C_ + h*HD_ + d];
        ctx[b*C_ + t] = s;
    }
}

// ---------------- output index mapping ----------------
// mode 0: plain row-major; mode 1: head-major; mode 2: xx rows 1..196; mode 3: xx row 0
__device__ __forceinline__ size_t out_map(int mode, int mm, int nn, int N)
{
    if (mode == 0) return (size_t)mm * N + nn;
    if (mode == 1) {
        int bq = mm / N_, n = mm % N_;
        return ((size_t)(bq*H_ + (nn >> 6)) * N_ + n) * HD_ + (nn & 63);
    }
    if (mode == 2) {
        int bq = mm / N_, n = mm % N_;
        return ((size_t)bq*T_ + 1 + n) * C_ + nn;
    }
    return (size_t)mm * T_ * C_ + nn; // mode 3
}

// ---------------- tf32 GEMM: out = act(A@W + bias) (+res), mapped ----------------
__global__ __launch_bounds__(256)
void gemm_tf32(const float* __restrict__ A, const float* __restrict__ W,
               const float* __restrict__ bias, const float* __restrict__ res,
               float* __restrict__ out, int M, int N, int K, int act, int mode)
{
    __shared__ float As[16*136];
    __shared__ float Bs[16*72];
    int tid = threadIdx.x;
    int lane = tid & 31, warp = tid >> 5;
    int gid = lane >> 2, tig = lane & 3;
    int wm = warp >> 1, wn = warp & 1;            // 4 x 2 warp grid, warp tile 32x32
    int m0 = blockIdx.y * 128, n0 = blockIdx.x * 64;

    int arow = tid & 63, akq = tid >> 6;
    int brow = tid >> 4, bcol = (tid & 15) * 4;

    float acc[2][4][4];
#pragma unroll
    for (int t = 0; t < 2; t++)
#pragma unroll
        for (int u = 0; u < 4; u++)
#pragma unroll
            for (int e = 0; e < 4; e++) acc[t][u][e] = 0.f;

    for (int kk0 = 0; kk0 < K; kk0 += 16) {
        __syncthreads();
#pragma unroll
        for (int i = 0; i < 2; i++) {
            int row = arow + i*64;
            float4 v = make_float4(0.f,0.f,0.f,0.f);
            if (m0 + row < M) v = *(const float4*)(A + (size_t)(m0+row)*K + kk0 + akq*4);
            As[(akq*4+0)*136 + row] = to_tf32(v.x);
            As[(akq*4+1)*136 + row] = to_tf32(v.y);
            As[(akq*4+2)*136 + row] = to_tf32(v.z);
            As[(akq*4+3)*136 + row] = to_tf32(v.w);
        }
        {
            float4 v = *(const float4*)(W + (size_t)(kk0+brow)*N + n0 + bcol);
            float4 c = make_float4(to_tf32(v.x), to_tf32(v.y), to_tf32(v.z), to_tf32(v.w));
            *(float4*)(Bs + brow*72 + bcol) = c;
        }
        __syncthreads();
#pragma unroll
        for (int ks = 0; ks < 2; ks++) {
            int k = ks*8;
            uint32_t a[2][4];
#pragma unroll
            for (int t = 0; t < 2; t++) {
                int mb = wm*32 + t*16;
                a[t][0] = U32(As[(k+tig)*136 + mb+gid]);
                a[t][1] = U32(As[(k+tig)*136 + mb+gid+8]);
                a[t][2] = U32(As[(k+tig+4)*136 + mb+gid]);
                a[t][3] = U32(As[(k+tig+4)*136 + mb+gid+8]);
            }
#pragma unroll
            for (int u = 0; u < 4; u++) {
                int cb = wn*32 + u*8;
                uint32_t b0 = U32(Bs[(k+tig)*72 + cb+gid]);
                uint32_t b1 = U32(Bs[(k+tig+4)*72 + cb+gid]);
                mma8(acc[0][u], a[0][0],a[0][1],a[0][2],a[0][3], b0,b1);
                mma8(acc[1][u], a[1][0],a[1][1],a[1][2],a[1][3], b0,b1);
            }
        }
    }
#pragma unroll
    for (int t = 0; t < 2; t++) {
#pragma unroll
        for (int u = 0; u < 4; u++) {
            int rb = m0 + wm*32 + t*16 + gid;
            int cb = n0 + wn*32 + u*8 + 2*tig;
#pragma unroll
            for (int e = 0; e < 4; e++) {
                int r = rb + (e >> 1) * 8;
                int c = cb + (e & 1);
                if (r < M) {
                    float v = acc[t][u][e];
                    if (bias) v += bias[c];
                    if (act) v = gelu_f(v);
                    size_t idx = out_map(mode, r, c, N);
                    if (res) v += res[idx];
                    out[idx] = v;
                }
            }
        }
    }
}

// ---------------- fused rectified attention core (tf32 mma) ----------------
// tmp[bh,n,p] = sum_c w2[b,h,c] * sum_m relu(-S*qh_n.kh_m) * relu(S*k2_m.q2_p)
__global__ __launch_bounds__(256)
void fused_attn_tf32(const float* __restrict__ qh, const float* __restrict__ kh,
                     const float* __restrict__ q2, const float* __restrict__ k2,
                     const float* __restrict__ w2all, float* __restrict__ tmp_out)
{
    extern __shared__ float sm[];
    float* qh_s = sm;            // [64][136]  (d-major, n-local cols 0..127)
    float* q2t  = sm + 8704;     // [64][136]  (d-major, p-local)
    float* kht  = sm + 17408;    // [64][24]   (d-major, m 0..15)
    float* k2t  = sm + 18944;    // [64][24]
    float* L_s  = sm + 20480;    // [16][136]  (m-major, n-local)
    float* R_s  = sm + 22656;    // [16][136]  (m-major, p-local)

    int tid = threadIdx.x;
    int lane = tid & 31, warp = tid >> 5;
    int gid = lane >> 2, tig = lane & 3;
    int wm = warp >> 1, wn = warp & 1;   // GEMM-3: 4x2 grid, warp tile 32x64

    int bh = blockIdx.z;
    int b = bh / H_, h = bh % H_;
    int n0 = blockIdx.y * 68;            // {0, 68}: exact cover of 196 with 128-tiles
    int p0 = blockIdx.x * 68;

    const float* qh_b = qh + (size_t)bh * N_ * HD_;
    const float* q2_b = q2 + (size_t)bh * N_ * HD_;

    for (int idx = tid; idx < 2048; idx += 256) {
        int r = idx & 127, dq = idx >> 7;
        float4 a = *(const float4*)(qh_b + (size_t)(n0+r)*HD_ + dq*4);
        qh_s[(dq*4+0)*136 + r] = to_tf32(a.x);
        qh_s[(dq*4+1)*136 + r] = to_tf32(a.y);
        qh_s[(dq*4+2)*136 + r] = to_tf32(a.z);
        qh_s[(dq*4+3)*136 + r] = to_tf32(a.w);
        float4 u4 = *(const float4*)(q2_b + (size_t)(p0+r)*HD_ + dq*4);
        q2t[(dq*4+0)*136 + r] = to_tf32(u4.x);
        q2t[(dq*4+1)*136 + r] = to_tf32(u4.y);
        q2t[(dq*4+2)*136 + r] = to_tf32(u4.z);
        q2t[(dq*4+3)*136 + r] = to_tf32(u4.w);
    }

    float acc[2][8][4];
#pragma unroll
    for (int t = 0; t < 2; t++)
#pragma unroll
        for (int u = 0; u < 8; u++)
#pragma unroll
            for (int e = 0; e < 4; e++) acc[t][u][e] = 0.f;

    int crow = tid & 15, cdq = tid >> 4;

    for (int c = 0; c < NC_; c++) {
        float w2c = w2all[b*CH_ + h*NC_ + c];
        const float* kh_c = kh + (size_t)(c*H_ + h) * N_ * HD_;
        const float* k2_c = k2 + (size_t)(c*H_ + h) * N_ * HD_;
        for (int m0c = 0; m0c < N_; m0c += 16) {
            __syncthreads();
            {
                int m = m0c + crow;
                float4 a = make_float4(0.f,0.f,0.f,0.f), bb = make_float4(0.f,0.f,0.f,0.f);
                if (m < N_) {
                    a  = *(const float4*)(kh_c + (size_t)m*HD_ + cdq*4);
                    bb = *(const float4*)(k2_c + (size_t)m*HD_ + cdq*4);
                }
                kht[(cdq*4+0)*24 + crow] = to_tf32(a.x);
                kht[(cdq*4+1)*24 + crow] = to_tf32(a.y);
                kht[(cdq*4+2)*24 + crow] = to_tf32(a.z);
                kht[(cdq*4+3)*24 + crow] = to_tf32(a.w);
                k2t[(cdq*4+0)*24 + crow] = to_tf32(bb.x);
                k2t[(cdq*4+1)*24 + crow] = to_tf32(bb.y);
                k2t[(cdq*4+2)*24 + crow] = to_tf32(bb.z);
                k2t[(cdq*4+3)*24 + crow] = to_tf32(bb.w);
            }
            __syncthreads();
            // GEMM-1: L[n=128, m=16] = Qh_tile . Kh_chunk^T ; each warp one m16-row-block
            {
                float lacc[2][4];
#pragma unroll
                for (int u = 0; u < 2; u++)
#pragma unroll
                    for (int e = 0; e < 4; e++) lacc[u][e] = 0.f;
#pragma unroll
                for (int ks = 0; ks < 8; ks++) {
                    int k = ks*8;
                    uint32_t a0 = U32(qh_s[(k+tig)*136 + warp*16 + gid]);
                    uint32_t a1 = U32(qh_s[(k+tig)*136 + warp*16 + gid + 8]);
                    uint32_t a2 = U32(qh_s[(k+tig+4)*136 + warp*16 + gid]);
                    uint32_t a3 = U32(qh_s[(k+tig+4)*136 + warp*16 + gid + 8]);
#pragma unroll
                    for (int u = 0; u < 2; u++) {
                        uint32_t b0 = U32(kht[(k+tig)*24 + u*8 + gid]);
                        uint32_t b1 = U32(kht[(k+tig+4)*24 + u*8 + gid]);
                        mma8(lacc[u], a0,a1,a2,a3, b0,b1);
                    }
                }
#pragma unroll
                for (int u = 0; u < 2; u++) {
                    int mc = u*8 + 2*tig;
                    int nr = warp*16 + gid;
                    L_s[mc*136 + nr]         = to_tf32(w2c * fmaxf(0.f, -SCALE_*lacc[u][0]));
                    L_s[(mc+1)*136 + nr]     = to_tf32(w2c * fmaxf(0.f, -SCALE_*lacc[u][1]));
                    L_s[mc*136 + nr + 8]     = to_tf32(w2c * fmaxf(0.f, -SCALE_*lacc[u][2]));
                    L_s[(mc+1)*136 + nr + 8] = to_tf32(w2c * fmaxf(0.f, -SCALE_*lacc[u][3]));
                }
            }
            // GEMM-2: R[m=16, p=128] = K2_chunk . Q2_tile^T ; each warp a 16-col slice of p
            {
                float racc[2][4];
#pragma unroll
                for (int u = 0; u < 2; u++)
#pragma unroll
                    for (int e = 0; e < 4; e++) racc[u][e] = 0.f;
#pragma unroll
                for (int ks = 0; ks < 8; ks++) {
                    int k = ks*8;
                    uint32_t a0 = U32(k2t[(k+tig)*24 + gid]);
                    uint32_t a1 = U32(k2t[(k+tig)*24 + gid + 8]);
                    uint32_t a2 = U32(k2t[(k+tig+4)*24 + gid]);
                    uint32_t a3 = U32(k2t[(k+tig+4)*24 + gid + 8]);
#pragma unroll
                    for (int u = 0; u < 2; u++) {
                        int cb = warp*16 + u*8;
                        uint32_t b0 = U32(q2t[(k+tig)*136 + cb + gid]);
                        uint32_t b1 = U32(q2t[(k+tig+4)*136 + cb + gid]);
                        mma8(racc[u], a0,a1,a2,a3, b0,b1);
                    }
                }
#pragma unroll
                for (int u = 0; u < 2; u++) {
                    int cb = warp*16 + u*8 + 2*tig;
                    R_s[gid*136 + cb]         = to_tf32(fmaxf(0.f, SCALE_*racc[u][0]));
                    R_s[gid*136 + cb + 1]     = to_tf32(fmaxf(0.f, SCALE_*racc[u][1]));
                    R_s[(gid+8)*136 + cb]     = to_tf32(fmaxf(0.f, SCALE_*racc[u][2]));
                    R_s[(gid+8)*136 + cb + 1] = to_tf32(fmaxf(0.f, SCALE_*racc[u][3]));
                }
            }
            __syncthreads();
            // GEMM-3: acc += L . R   (K=16)
#pragma unroll
            for (int ks = 0; ks < 2; ks++) {
                int k = ks*8;
                uint32_t a[2][4];
#pragma unroll
                for (int t = 0; t < 2; t++) {
                    int mb = wm*32 + t*16;
                    a[t][0] = U32(L_s[(k+tig)*136 + mb + gid]);
                    a[t][1] = U32(L_s[(k+tig)*136 + mb + gid + 8]);
                    a[t][2] = U32(L_s[(k+tig+4)*136 + mb + gid]);
                    a[t][3] = U32(L_s[(k+tig+4)*136 + mb + gid + 8]);
                }
#pragma unroll
                for (int u = 0; u < 8; u++) {
                    int cb = wn*64 + u*8;
                    uint32_t b0 = U32(R_s[(k+tig)*136 + cb + gid]);
                    uint32_t b1 = U32(R_s[(k+tig+4)*136 + cb + gid]);
                    mma8(acc[0][u], a[0][0],a[0][1],a[0][2],a[0][3], b0,b1);
                    mma8(acc[1][u], a[1][0],a[1][1],a[1][2],a[1][3], b0,b1);
                }
            }
        }
    }

    float* o = tmp_out + (size_t)bh * N_ * N_;
#pragma unroll
    for (int t = 0; t < 2; t++) {
#pragma unroll
        for (int u = 0; u < 8; u++) {
            int n = n0 + wm*32 + t*16 + gid;
            int p = p0 + wn*64 + u*8 + 2*tig;
            o[(size_t)n*N_ + p]           = acc[t][u][0];
            o[(size_t)n*N_ + p + 1]       = acc[t][u][1];
            o[(size_t)(n+8)*N_ + p]       = acc[t][u][2];
            o[(size_t)(n+8)*N_ + p + 1]   = acc[t][u][3];
        }
    }
}

// ---------------- rect = tmp @ vr (per b,h) ----------------
__global__ __launch_bounds__(256)
void rect_kernel(const float* __restrict__ tmp, const float* __restrict__ vr,
                 float* __restrict__ rectH)
{
    extern __shared__ float sm[];
    float* vr_s  = sm;            // [196][64]
    float* tmp_s = sm + N_*HD_;   // [4][196]
    int bh = blockIdx.y;
    int r0 = blockIdx.x * 4;
    const float* vrb = vr + (size_t)bh * N_ * HD_;
    for (int i = threadIdx.x; i < N_*HD_/4; i += 256)
        ((float4*)vr_s)[i] = ((const float4*)vrb)[i];
    const float* tb = tmp + (size_t)bh * N_ * N_;
    for (int i = threadIdx.x; i < 4*N_; i += 256) {
        int rr = i / N_, kk = i % N_;
        tmp_s[i] = tb[(size_t)(r0 + rr)*N_ + kk];
    }
    __syncthreads();
    int d = threadIdx.x & 63, rr = threadIdx.x >> 6;
    float a = 0.f;
    for (int kk = 0; kk < N_; kk++) a += tmp_s[rr*N_ + kk] * vr_s[kk*HD_ + d];
    rectH[(size_t)bh*N_*HD_ + (size_t)(r0 + rr)*HD_ + d] = a;
}

// ---------------- anchor copy ----------------
__global__ void copy_kernel(const float* __restrict__ src, float* __restrict__ dst, int n4)
{
    int i = blockIdx.x * blockDim.x + threadIdx.x;
    if (i < n4) ((float4*)dst)[i] = ((const float4*)src)[i];
}

// ---------------- launch ----------------
extern "C" void kernel_launch(void* const* d_in, const int* in_sizes, int n_in,
                              void* d_out, int out_size)
{
    const float* x       = (const float*)d_in[0];
    const float* Wqv     = (const float*)d_in[1];
    const float* Wk      = (const float*)d_in[2];
    const float* Wq_proj = (const float*)d_in[3];
    const float* bq_proj = (const float*)d_in[4];
    const float* Wqk     = (const float*)d_in[5];
    const float* Wqk2    = (const float*)d_in[6];
    const float* Wv      = (const float*)d_in[7];
    const float* Wr_proj = (const float*)d_in[8];
    const float* br_proj = (const float*)d_in[9];
    const float* g1      = (const float*)d_in[10];
    const float* b1      = (const float*)d_in[11];
    const float* g2      = (const float*)d_in[12];
    const float* b2      = (const float*)d_in[13];
    const float* g3      = (const float*)d_in[14];
    const float* b3      = (const float*)d_in[15];
    const float* W1      = (const float*)d_in[16];
    const float* bm1     = (const float*)d_in[17];
    const float* W2      = (const float*)d_in[18];
    const float* bm2     = (const float*)d_in[19];
    float* outp = (float*)d_out;

    float *n1, *n2x, *n2a, *qv, *kb, *attn, *ctx, *qh, *q2, *vrp, *khp, *k2p;
    float *tmp, *rectH, *xx, *hdn, *h1;
    cudaGetSymbolAddress((void**)&n1, g_n1);
    cudaGetSymbolAddress((void**)&n2x, g_n2x);
    cudaGetSymbolAddress((void**)&n2a, g_n2a);
    cudaGetSymbolAddress((void**)&qv, g_qv);
    cudaGetSymbolAddress((void**)&kb, g_k);
    cudaGetSymbolAddress((void**)&attn, g_attn);
    cudaGetSymbolAddress((void**)&ctx, g_ctx);
    cudaGetSymbolAddress((void**)&qh, g_qh);
    cudaGetSymbolAddress((void**)&q2, g_q2);
    cudaGetSymbolAddress((void**)&vrp, g_vr);
    cudaGetSymbolAddress((void**)&khp, g_kh);
    cudaGetSymbolAddress((void**)&k2p, g_k2);
    cudaGetSymbolAddress((void**)&tmp, g_tmp);
    cudaGetSymbolAddress((void**)&rectH, g_rectH);
    cudaGetSymbolAddress((void**)&xx, g_xx);
    cudaGetSymbolAddress((void**)&hdn, g_hdn);
    cudaGetSymbolAddress((void**)&h1, g_h1);

    const int SMEM_F = 24832 * 4;
    const int SMEM_R = (N_*HD_ + 4*N_) * 4;
    cudaFuncSetAttribute(fused_attn_tf32, cudaFuncAttributeMaxDynamicSharedMemorySize, SMEM_F);
    cudaFuncSetAttribute(rect_kernel, cudaFuncAttributeMaxDynamicSharedMemorySize, SMEM_R);

    // 1) LayerNorms
    ln_kernel<<<26, 128>>>(x, n1, g1, b1, 26, 26, 0, (long)T_*C_);
    ln_kernel<<<B_*N_, 128>>>(x + C_, n2x, g2, b2, B_*N_, N_, (long)T_*C_, C_);
    ln_kernel<<<NC_*N_, 128>>>(x + (long)16*T_*C_ + C_, n2a, g2, b2, NC_*N_, N_, (long)T_*C_, C_);

    // 2) cls path: qv = n1a@Wqv, k = n1x@Wk (tensor-core GEMMs)
    gemm_tf32<<<dim3(12,1), 256>>>(n1 + 16*C_, Wqv, nullptr, nullptr, qv, NC_, 2*C_, C_, 0, 0);
    gemm_tf32<<<dim3(6,1), 256>>>(n1, Wk, nullptr, nullptr, kb, B_, C_, C_, 0, 0);
    attn_cls_kernel<<<B_, 384>>>(qv, kb, attn, ctx);
    gemm_tf32<<<dim3(6,1), 256>>>(ctx, Wq_proj, bq_proj, nullptr, xx, B_, C_, C_, 0, 3);

    // 3) head projections (head-major outputs)
    dim3 gx(6, 25), ga(6, 16);
    gemm_tf32<<<gx, 256>>>(n2x, Wqk,  nullptr, nullptr, qh,  B_*N_, C_, C_, 0, 1);
    gemm_tf32<<<gx, 256>>>(n2x, Wqk2, nullptr, nullptr, q2,  B_*N_, C_, C_, 0, 1);
    gemm_tf32<<<gx, 256>>>(n2x, Wv,   nullptr, nullptr, vrp, B_*N_, C_, C_, 0, 1);
    gemm_tf32<<<ga, 256>>>(n2a, Wqk,  nullptr, nullptr, khp, NC_*N_, C_, C_, 0, 1);
    gemm_tf32<<<ga, 256>>>(n2a, Wqk2, nullptr, nullptr, k2p, NC_*N_, C_, C_, 0, 1);

    // 4) fused rectified attention core (tensor cores)
    dim3 gf(2, 2, BH_);
    fused_attn_tf32<<<gf, 256, SMEM_F>>>(qh, khp, q2, k2p, attn, tmp);

    // 5) rect = tmp @ vr
    dim3 gr(49, BH_);
    rect_kernel<<<gr, 256, SMEM_R>>>(tmp, vrp, rectH);

    // 6) rect projection + residual -> xx rows 1..196
    gemm_tf32<<<gx, 256>>>(rectH, Wr_proj, br_proj, x, xx, B_*N_, C_, C_, 0, 2);

    // 7) MLP
    ln_kernel<<<B_*T_, 128>>>(xx, hdn, g3, b3, B_*T_, B_*T_, 0, C_);
    dim3 gm1(24, 25), gm2(6, 25);
    gemm_tf32<<<gm1, 256>>>(hdn, W1, bm1, nullptr, h1, B_*T_, 4*C_, C_, 1, 0);
    gemm_tf32<<<gm2, 256>>>(h1, W2, bm2, xx, outp, B_*T_, C_, 4*C_, 0, 0);

    // 8) anchors pass-through
    int n4 = NC_*T_*C_/4;
    copy_kernel<<<(n4 + 255)/256, 256>>>(x + (long)16*T_*C_, outp + (long)16*T_*C_, n4);
}

// round 4
// speedup vs baseline: 1.3769x; 1.3769x over previous
#include <cuda_runtime.h>
#include <cstdint>

#define B_  16
#define NC_ 10
#define H_  6
#define C_  384
#define HD_ 64
#define T_  197
#define N_  196
#define BH_ (B_*H_)
#define CH_ (NC_*H_)
#define SCALE_ 0.125f

__device__ float g_n1 [26*C_];
__device__ float g_n2x[B_*N_*C_];
__device__ float g_n2a[NC_*N_*C_];
__device__ float g_qv [NC_*2*C_];
__device__ float g_k  [B_*C_];
__device__ float g_attn[B_*CH_];
__device__ float g_ctx[B_*C_];
__device__ float g_qh [BH_*N_*HD_];
__device__ float g_q2 [BH_*N_*HD_];
__device__ float g_vr [BH_*N_*HD_];
__device__ float g_kh [CH_*N_*HD_];
__device__ float g_k2 [CH_*N_*HD_];
__device__ float g_tmp[BH_*N_*N_];
__device__ float g_rectH[B_*N_*C_];
__device__ float g_xx [B_*T_*C_];
__device__ float g_hdn[B_*T_*C_];
__device__ float g_h1 [B_*T_*4*C_];

__device__ __forceinline__ float to_tf32(float x) {
    uint32_t u;
    asm("cvt.rna.tf32.f32 %0, %1;" : "=r"(u) : "f"(x));
    return __uint_as_float(u);
}
#define U32(x) __float_as_uint(x)

__device__ __forceinline__ void mma8(float* c, uint32_t a0, uint32_t a1, uint32_t a2, uint32_t a3,
                                     uint32_t b0, uint32_t b1)
{
    asm volatile("mma.sync.aligned.m16n8k8.row.col.f32.tf32.tf32.f32 "
                 "{%0,%1,%2,%3},{%4,%5,%6,%7},{%8,%9},{%0,%1,%2,%3};\n"
                 : "+f"(c[0]), "+f"(c[1]), "+f"(c[2]), "+f"(c[3])
                 : "r"(a0), "r"(a1), "r"(a2), "r"(a3), "r"(b0), "r"(b1));
}

__device__ __forceinline__ void cp16(uint32_t dst, const void* src, bool p) {
    int sz = p ? 16 : 0;
    asm volatile("cp.async.cg.shared.global [%0], [%1], 16, %2;" :: "r"(dst), "l"(src), "r"(sz));
}

__device__ __forceinline__ float gelu_f(float x) {
    return 0.5f * x * (1.f + erff(x * 0.7071067811865475f));
}

// ---------------- LayerNorm ----------------
__global__ void ln_kernel(const float* __restrict__ in, float* __restrict__ out,
                          const float* __restrict__ g, const float* __restrict__ bt,
                          int rows, int inner, long outer_stride, long inner_stride)
{
    int row = blockIdx.x;
    if (row >= rows) return;
    const float* src = in + (long)(row / inner) * outer_stride + (long)(row % inner) * inner_stride;
    int t = threadIdx.x;
    float v[3]; float s = 0.f;
#pragma unroll
    for (int i = 0; i < 3; i++) { v[i] = src[t + i*128]; s += v[i]; }
    __shared__ float red[4];
#pragma unroll
    for (int o = 16; o > 0; o >>= 1) s += __shfl_xor_sync(0xffffffffu, s, o);
    if ((t & 31) == 0) red[t >> 5] = s;
    __syncthreads();
    float mean = (red[0] + red[1] + red[2] + red[3]) * (1.f/384.f);
    float q = 0.f;
#pragma unroll
    for (int i = 0; i < 3; i++) { float d = v[i] - mean; q += d*d; }
#pragma unroll
    for (int o = 16; o > 0; o >>= 1) q += __shfl_xor_sync(0xffffffffu, q, o);
    __syncthreads();
    if ((t & 31) == 0) red[t >> 5] = q;
    __syncthreads();
    float var = (red[0] + red[1] + red[2] + red[3]) * (1.f/384.f);
    float rs = rsqrtf(var + 1e-5f);
    float* dst = out + (long)row * C_;
#pragma unroll
    for (int i = 0; i < 3; i++) { int c = t + i*128; dst[c] = (v[i] - mean) * rs * g[c] + bt[c]; }
}

// ---------------- small-M row GEMM (cls path), K=384, 256 threads ----------------
__global__ __launch_bounds__(256)
void rowgemm(const float* __restrict__ A, const float* __restrict__ W,
             const float* __restrict__ bias, float* __restrict__ out,
             int N, long out_stride)
{
    __shared__ float a_s[384];
    __shared__ float part[128];
    int row = blockIdx.x, cb = blockIdx.y * 128;
    int t = threadIdx.x;
    for (int i = t; i < 384; i += 256) a_s[i] = A[(size_t)row*384 + i];
    __syncthreads();
    int half = t >> 7, c = t & 127;
    float s = 0.f;
    const float* Wp = W + (size_t)(half*192)*N + cb + c;
#pragma unroll 8
    for (int k = 0; k < 192; k++) s += a_s[half*192 + k] * Wp[(size_t)k*N];
    if (half) part[c] = s;
    __syncthreads();
    if (!half) {
        float v = s + part[c];
        if (bias) v += bias[cb + c];
        out[(size_t)row*out_stride + cb + c] = v;
    }
}

// ---------------- cls attention ----------------
__global__ void attn_cls_kernel(const float* __restrict__ qv, const float* __restrict__ k,
                                float* __restrict__ attn, float* __restrict__ ctx)
{
    int b = blockIdx.x, t = threadIdx.x;
    __shared__ float sl[CH_];
    if (t < CH_) {
        int n = t / H_, h = t % H_;
        float s = 0.f;
        for (int d = 0; d < HD_; d++) s += qv[n*2*C_ + h*HD_ + d] * k[b*C_ + h*HD_ + d];
        sl[t] = s * SCALE_;
    }
    __syncthreads();
    if (t < H_) {
        float mx = -1e30f;
        for (int n = 0; n < NC_; n++) mx = fmaxf(mx, sl[n*H_ + t]);
        float sum = 0.f;
        for (int n = 0; n < NC_; n++) { float e = expf(sl[n*H_ + t] - mx); sl[n*H_ + t] = e; sum += e; }
        float inv = 1.f / sum;
        for (int n = 0; n < NC_; n++) { sl[n*H_ + t] *= inv; attn[b*CH_ + n*H_ + t] = sl[n*H_ + t]; }
    }
    __syncthreads();
    {
        int h = t >> 6, d = t & 63;
        float s = 0.f;
        for (int n = 0; n < NC_; n++) s += sl[n*H_ + h] * qv[n*2*C_ + C_ + h*HD_ + d];
        ctx[b*C_ + t] = s;
    }
}

// 0: row-major; 1: head-major (tf32-rounded); 2: xx rows 1..196
__device__ __forceinline__ size_t out_map(int mode, int mm, int nn, int N)
{
    if (mode == 0) return (size_t)mm * N + nn;
    if (mode == 1) {
        int bq = mm / N_, n = mm % N_;
        return ((size_t)(bq*H_ + (nn >> 6)) * N_ + n) * HD_ + (nn & 63);
    }
    int bq = mm / N_, n = mm % N_;
    return ((size_t)bq*T_ + 1 + n) * C_ + nn;
}

// ---------------- tf32 GEMM 128x64 tile, batched via grid.z ----------------
__global__ __launch_bounds__(256)
void gemm_tf32(const float* __restrict__ A, const float* __restrict__ W,
               const float* __restrict__ bias, const float* __restrict__ res,
               float* __restrict__ out, int M, int N, int K, int act, int mode,
               long zA, long zB, long zO)
{
    __shared__ float As[16*136];
    __shared__ float Bs[16*72];
    A   += (size_t)blockIdx.z * zA;
    W   += (size_t)blockIdx.z * zB;
    out += (size_t)blockIdx.z * zO;
    int tid = threadIdx.x;
    int lane = tid & 31, warp = tid >> 5;
    int gid = lane >> 2, tig = lane & 3;
    int wm = warp >> 1, wn = warp & 1;
    int m0 = blockIdx.y * 128, n0 = blockIdx.x * 64;
    int arow = tid & 63, akq = tid >> 6;
    int brow = tid >> 4, bcol = (tid & 15) * 4;

    float acc[2][4][4];
#pragma unroll
    for (int t = 0; t < 2; t++)
#pragma unroll
        for (int u = 0; u < 4; u++)
#pragma unroll
            for (int e = 0; e < 4; e++) acc[t][u][e] = 0.f;

    for (int kk0 = 0; kk0 < K; kk0 += 16) {
        __syncthreads();
#pragma unroll
        for (int i = 0; i < 2; i++) {
            int row = arow + i*64;
            float4 v = make_float4(0.f,0.f,0.f,0.f);
            if (m0 + row < M && kk0 + akq*4 + 4 <= K)
                v = *(const float4*)(A + (size_t)(m0+row)*K + kk0 + akq*4);
            As[(akq*4+0)*136 + row] = to_tf32(v.x);
            As[(akq*4+1)*136 + row] = to_tf32(v.y);
            As[(akq*4+2)*136 + row] = to_tf32(v.z);
            As[(akq*4+3)*136 + row] = to_tf32(v.w);
        }
        {
            float4 v = make_float4(0.f,0.f,0.f,0.f);
            if (kk0 + brow < K)
                v = *(const float4*)(W + (size_t)(kk0+brow)*N + n0 + bcol);
            float4 c = make_float4(to_tf32(v.x), to_tf32(v.y), to_tf32(v.z), to_tf32(v.w));
            *(float4*)(Bs + brow*72 + bcol) = c;
        }
        __syncthreads();
#pragma unroll
        for (int ks = 0; ks < 2; ks++) {
            int k = ks*8;
            uint32_t a[2][4];
#pragma unroll
            for (int t = 0; t < 2; t++) {
                int mb = wm*32 + t*16;
                a[t][0] = U32(As[(k+tig)*136 + mb+gid]);
                a[t][1] = U32(As[(k+tig)*136 + mb+gid+8]);
                a[t][2] = U32(As[(k+tig+4)*136 + mb+gid]);
                a[t][3] = U32(As[(k+tig+4)*136 + mb+gid+8]);
            }
#pragma unroll
            for (int u = 0; u < 4; u++) {
                int cb = wn*32 + u*8;
                uint32_t b0 = U32(Bs[(k+tig)*72 + cb+gid]);
                uint32_t b1 = U32(Bs[(k+tig+4)*72 + cb+gid]);
                mma8(acc[0][u], a[0][0],a[0][1],a[0][2],a[0][3], b0,b1);
                mma8(acc[1][u], a[1][0],a[1][1],a[1][2],a[1][3], b0,b1);
            }
        }
    }
#pragma unroll
    for (int t = 0; t < 2; t++) {
#pragma unroll
        for (int u = 0; u < 4; u++) {
            int rb = m0 + wm*32 + t*16 + gid;
            int cb = n0 + wn*32 + u*8 + 2*tig;
#pragma unroll
            for (int e = 0; e < 4; e++) {
                int r = rb + (e >> 1) * 8;
                int c = cb + (e & 1);
                if (r < M) {
                    float v = acc[t][u][e];
                    if (bias) v += bias[c];
                    if (act) v = gelu_f(v);
                    if (mode == 1) v = to_tf32(v);
                    size_t idx = out_map(mode, r, c, N);
                    if (res) v += res[idx];
                    out[idx] = v;
                }
            }
        }
    }
}

// ---------------- fused rectified attention core ----------------
// tmp[bh,n,p] = sum_c w2[b,h,c] * sum_m relu(-S*qh_n.kh_m) * relu(S*k2_m.q2_p)
// inputs qh/q2/kh/k2 are pre-rounded to tf32.
__global__ __launch_bounds__(256, 1)
void fused_attn2(const float* __restrict__ qh, const float* __restrict__ kh,
                 const float* __restrict__ q2, const float* __restrict__ k2,
                 const float* __restrict__ w2all, float* __restrict__ tmp_out)
{
    __shared__ float sm_[8704];
    float* const kbuf0 = sm_;            // [16][68]
    float* const kbuf1 = sm_ + 1088;
    float* const vbuf0 = sm_ + 2176;
    float* const vbuf1 = sm_ + 3264;
    float* const L_s   = sm_ + 4352;     // [16][136] L[m][n]
    float* const R_s   = sm_ + 6528;     // [16][136] R[m][p]

    int tid = threadIdx.x;
    int lane = tid & 31, warp = tid >> 5;
    int gid = lane >> 2, tig = lane & 3;
    int wm = warp >> 1, wn = warp & 1;

    int bh = blockIdx.z;
    int b = bh / H_, h = bh % H_;
    int n0 = blockIdx.y * 68;
    int p0 = blockIdx.x * 68;

    const float* qh_b = qh + (size_t)bh * N_ * HD_;
    const float* q2_b = q2 + (size_t)bh * N_ * HD_;

    // stage qh tile row-major [128][68], capture A-frags (rows warp*16..+16)
    uint32_t aq[8][4];
    for (int i = tid; i < 2048; i += 256) {
        int r = i >> 4, c4 = (i & 15) * 4;
        *(float4*)(sm_ + r*68 + c4) = *(const float4*)(qh_b + (size_t)(n0+r)*HD_ + c4);
    }
    __syncthreads();
    {
        int rb = warp * 16;
#pragma unroll
        for (int j = 0; j < 8; j++) {
            aq[j][0] = U32(sm_[(rb+gid)*68 + 8*j+tig]);
            aq[j][1] = U32(sm_[(rb+gid+8)*68 + 8*j+tig]);
            aq[j][2] = U32(sm_[(rb+gid)*68 + 8*j+tig+4]);
            aq[j][3] = U32(sm_[(rb+gid+8)*68 + 8*j+tig+4]);
        }
    }
    __syncthreads();
    // stage q2 tile, capture B-frags (cols = p-strip warp*16..+16)
    uint32_t bq[8][2][2];
    for (int i = tid; i < 2048; i += 256) {
        int r = i >> 4, c4 = (i & 15) * 4;
        *(float4*)(sm_ + r*68 + c4) = *(const float4*)(q2_b + (size_t)(p0+r)*HD_ + c4);
    }
    __syncthreads();
    {
        int pb = warp * 16;
#pragma unroll
        for (int j = 0; j < 8; j++)
#pragma unroll
            for (int t = 0; t < 2; t++) {
                bq[j][t][0] = U32(sm_[(pb+8*t+gid)*68 + 8*j+tig]);
                bq[j][t][1] = U32(sm_[(pb+8*t+gid)*68 + 8*j+tig+4]);
            }
    }
    __syncthreads();

    float acc[2][8][4];
#pragma unroll
    for (int t = 0; t < 2; t++)
#pragma unroll
        for (int u = 0; u < 8; u++)
#pragma unroll
            for (int e = 0; e < 4; e++) acc[t][u][e] = 0.f;

    uint32_t kd0 = (uint32_t)__cvta_generic_to_shared(kbuf0);
    uint32_t kd1 = (uint32_t)__cvta_generic_to_shared(kbuf1);
    uint32_t vd0 = (uint32_t)__cvta_generic_to_shared(vbuf0);
    uint32_t vd1 = (uint32_t)__cvta_generic_to_shared(vbuf1);
    int prow = tid >> 4, pc4 = (tid & 15) * 4;

    // prefetch chunk (c=0, mc=0) into buf0
    {
        const float* kh_c = kh + (size_t)h * N_ * HD_;
        const float* k2_c = k2 + (size_t)h * N_ * HD_;
        cp16(kd0 + (prow*68 + pc4)*4, kh_c + (size_t)prow*HD_ + pc4, true);
        cp16(vd0 + (prow*68 + pc4)*4, k2_c + (size_t)prow*HD_ + pc4, true);
    }
    asm volatile("cp.async.commit_group;" ::: "memory");

    int buf = 0;
    for (int c = 0; c < NC_; c++) {
        float w2c = w2all[b*CH_ + h*NC_ + c];
        for (int mc = 0; mc < 13; mc++) {
            // prefetch next chunk into buf^1
            {
                int nc2 = c, nm = mc + 1;
                if (nm == 13) { nm = 0; nc2 = c + 1; }
                if (nc2 < NC_) {
                    const float* kh_c = kh + (size_t)(nc2*H_ + h) * N_ * HD_;
                    const float* k2_c = k2 + (size_t)(nc2*H_ + h) * N_ * HD_;
                    int m = nm*16 + prow;
                    bool ok = m < N_;
                    size_t off = ok ? ((size_t)m*HD_ + pc4) : 0;
                    uint32_t kd = buf ? kd0 : kd1;
                    uint32_t vd = buf ? vd0 : vd1;
                    cp16(kd + (prow*68 + pc4)*4, kh_c + off, ok);
                    cp16(vd + (prow*68 + pc4)*4, k2_c + off, ok);
                }
            }
            asm volatile("cp.async.commit_group;" ::: "memory");
            asm volatile("cp.async.wait_group 1;" ::: "memory");
            __syncthreads();

            const float* KT  = buf ? kbuf1 : kbuf0;
            const float* K2T = buf ? vbuf1 : vbuf0;

            // GEMM-1: warp strip of L (n 16 x m 16)
            float lacc[2][4];
#pragma unroll
            for (int t = 0; t < 2; t++)
#pragma unroll
                for (int e = 0; e < 4; e++) lacc[t][e] = 0.f;
#pragma unroll
            for (int j = 0; j < 8; j++) {
#pragma unroll
                for (int t = 0; t < 2; t++) {
                    uint32_t b0 = U32(KT[(8*t+gid)*68 + 8*j+tig]);
                    uint32_t b1 = U32(KT[(8*t+gid)*68 + 8*j+tig+4]);
                    mma8(lacc[t], aq[j][0],aq[j][1],aq[j][2],aq[j][3], b0,b1);
                }
            }
            // GEMM-2: warp strip of R (m 16 x p 16)
            float racc[2][4];
#pragma unroll
            for (int t = 0; t < 2; t++)
#pragma unroll
                for (int e = 0; e < 4; e++) racc[t][e] = 0.f;
#pragma unroll
            for (int j = 0; j < 8; j++) {
                uint32_t a0 = U32(K2T[gid*68 + 8*j+tig]);
                uint32_t a1 = U32(K2T[(gid+8)*68 + 8*j+tig]);
                uint32_t a2 = U32(K2T[gid*68 + 8*j+tig+4]);
                uint32_t a3 = U32(K2T[(gid+8)*68 + 8*j+tig+4]);
                mma8(racc[0], a0,a1,a2,a3, bq[j][0][0], bq[j][0][1]);
                mma8(racc[1], a0,a1,a2,a3, bq[j][1][0], bq[j][1][1]);
            }
            {
                int nr = warp*16 + gid;
#pragma unroll
                for (int t = 0; t < 2; t++) {
                    int mcol = 8*t + 2*tig;
                    L_s[mcol*136 + nr]       = to_tf32(w2c * fmaxf(0.f, -SCALE_*lacc[t][0]));
                    L_s[(mcol+1)*136 + nr]   = to_tf32(w2c * fmaxf(0.f, -SCALE_*lacc[t][1]));
                    L_s[mcol*136 + nr+8]     = to_tf32(w2c * fmaxf(0.f, -SCALE_*lacc[t][2]));
                    L_s[(mcol+1)*136 + nr+8] = to_tf32(w2c * fmaxf(0.f, -SCALE_*lacc[t][3]));
                    int pc = warp*16 + 8*t + 2*tig;
                    float2 lo = make_float2(to_tf32(fmaxf(0.f, SCALE_*racc[t][0])),
                                            to_tf32(fmaxf(0.f, SCALE_*racc[t][1])));
                    float2 hi = make_float2(to_tf32(fmaxf(0.f, SCALE_*racc[t][2])),
                                            to_tf32(fmaxf(0.f, SCALE_*racc[t][3])));
                    *(float2*)(R_s + gid*136 + pc)     = lo;
                    *(float2*)(R_s + (gid+8)*136 + pc) = hi;
                }
            }
            __syncthreads();
            // GEMM-3: acc += L . R  (K=16)
#pragma unroll
            for (int g = 0; g < 2; g++) {
                uint32_t a[2][4];
#pragma unroll
                for (int t = 0; t < 2; t++) {
                    int mb = wm*32 + t*16;
                    a[t][0] = U32(L_s[(8*g+tig)*136 + mb+gid]);
                    a[t][1] = U32(L_s[(8*g+tig)*136 + mb+gid+8]);
                    a[t][2] = U32(L_s[(8*g+tig+4)*136 + mb+gid]);
                    a[t][3] = U32(L_s[(8*g+tig+4)*136 + mb+gid+8]);
                }
#pragma unroll
                for (int u = 0; u < 8; u++) {
                    int cb = wn*64 + u*8;
                    uint32_t b0 = U32(R_s[(8*g+tig)*136 + cb+gid]);
                    uint32_t b1 = U32(R_s[(8*g+tig+4)*136 + cb+gid]);
                    mma8(acc[0][u], a[0][0],a[0][1],a[0][2],a[0][3], b0,b1);
                    mma8(acc[1][u], a[1][0],a[1][1],a[1][2],a[1][3], b0,b1);
                }
            }
            buf ^= 1;
        }
    }

    float* o = tmp_out + (size_t)bh * N_ * N_;
#pragma unroll
    for (int t = 0; t < 2; t++) {
#pragma unroll
        for (int u = 0; u < 8; u++) {
            int n = n0 + wm*32 + t*16 + gid;
            int p = p0 + wn*64 + u*8 + 2*tig;
            o[(size_t)n*N_ + p]         = acc[t][u][0];
            o[(size_t)n*N_ + p + 1]     = acc[t][u][1];
            o[(size_t)(n+8)*N_ + p]     = acc[t][u][2];
            o[(size_t)(n+8)*N_ + p + 1] = acc[t][u][3];
        }
    }
}

__global__ void copy_kernel(const float* __restrict__ src, float* __restrict__ dst, int n4)
{
    int i = blockIdx.x * blockDim.x + threadIdx.x;
    if (i < n4) ((float4*)dst)[i] = ((const float4*)src)[i];
}

extern "C" void kernel_launch(void* const* d_in, const int* in_sizes, int n_in,
                              void* d_out, int out_size)
{
    const float* x       = (const float*)d_in[0];
    const float* Wqv     = (const float*)d_in[1];
    const float* Wk      = (const float*)d_in[2];
    const float* Wq_proj = (const float*)d_in[3];
    const float* bq_proj = (const float*)d_in[4];
    const float* Wqk     = (const float*)d_in[5];
    const float* Wqk2    = (const float*)d_in[6];
    const float* Wv      = (const float*)d_in[7];
    const float* Wr_proj = (const float*)d_in[8];
    const float* br_proj = (const float*)d_in[9];
    const float* g1      = (const float*)d_in[10];
    const float* b1      = (const float*)d_in[11];
    const float* g2      = (const float*)d_in[12];
    const float* b2      = (const float*)d_in[13];
    const float* g3      = (const float*)d_in[14];
    const float* b3      = (const float*)d_in[15];
    const float* W1      = (const float*)d_in[16];
    const float* bm1     = (const float*)d_in[17];
    const float* W2      = (const float*)d_in[18];
    const float* bm2     = (const float*)d_in[19];
    float* outp = (float*)d_out;

    float *n1, *n2x, *n2a, *qv, *kb, *attn, *ctx, *qh, *q2, *vrp, *khp, *k2p;
    float *tmp, *rectH, *xx, *hdn, *h1;
    cudaGetSymbolAddress((void**)&n1, g_n1);
    cudaGetSymbolAddress((void**)&n2x, g_n2x);
    cudaGetSymbolAddress((void**)&n2a, g_n2a);
    cudaGetSymbolAddress((void**)&qv, g_qv);
    cudaGetSymbolAddress((void**)&kb, g_k);
    cudaGetSymbolAddress((void**)&attn, g_attn);
    cudaGetSymbolAddress((void**)&ctx, g_ctx);
    cudaGetSymbolAddress((void**)&qh, g_qh);
    cudaGetSymbolAddress((void**)&q2, g_q2);
    cudaGetSymbolAddress((void**)&vrp, g_vr);
    cudaGetSymbolAddress((void**)&khp, g_kh);
    cudaGetSymbolAddress((void**)&k2p, g_k2);
    cudaGetSymbolAddress((void**)&tmp, g_tmp);
    cudaGetSymbolAddress((void**)&rectH, g_rectH);
    cudaGetSymbolAddress((void**)&xx, g_xx);
    cudaGetSymbolAddress((void**)&hdn, g_hdn);
    cudaGetSymbolAddress((void**)&h1, g_h1);

    // 1) LayerNorms
    ln_kernel<<<26, 128>>>(x, n1, g1, b1, 26, 26, 0, (long)T_*C_);
    ln_kernel<<<B_*N_, 128>>>(x + C_, n2x, g2, b2, B_*N_, N_, (long)T_*C_, C_);
    ln_kernel<<<NC_*N_, 128>>>(x + (long)16*T_*C_ + C_, n2a, g2, b2, NC_*N_, N_, (long)T_*C_, C_);

    // 2) cls path (row-parallel small GEMMs)
    rowgemm<<<dim3(NC_, 6), 256>>>(n1 + 16*C_, Wqv, nullptr, qv, 2*C_, 2*C_);
    rowgemm<<<dim3(B_, 3), 256>>>(n1, Wk, nullptr, kb, C_, C_);
    attn_cls_kernel<<<B_, 384>>>(qv, kb, attn, ctx);
    rowgemm<<<dim3(B_, 3), 256>>>(ctx, Wq_proj, bq_proj, xx, C_, (long)T_*C_);

    // 3) head projections (head-major, tf32-rounded outputs)
    dim3 gx(6, 25), ga(6, 16);
    gemm_tf32<<<gx, 256>>>(n2x, Wqk,  nullptr, nullptr, qh,  B_*N_, C_, C_, 0, 1, 0,0,0);
    gemm_tf32<<<gx, 256>>>(n2x, Wqk2, nullptr, nullptr, q2,  B_*N_, C_, C_, 0, 1, 0,0,0);
    gemm_tf32<<<gx, 256>>>(n2x, Wv,   nullptr, nullptr, vrp, B_*N_, C_, C_, 0, 1, 0,0,0);
    gemm_tf32<<<ga, 256>>>(n2a, Wqk,  nullptr, nullptr, khp, NC_*N_, C_, C_, 0, 1, 0,0,0);
    gemm_tf32<<<ga, 256>>>(n2a, Wqk2, nullptr, nullptr, k2p, NC_*N_, C_, C_, 0, 1, 0,0,0);

    // 4) fused rectified attention core
    dim3 gf(2, 2, BH_);
    fused_attn2<<<gf, 256>>>(qh, khp, q2, k2p, attn, tmp);

    // 5) rect = tmp @ vr, batched over bh (K=196, guarded)
    dim3 grc(1, 2, BH_);
    gemm_tf32<<<grc, 256>>>(tmp, vrp, nullptr, nullptr, rectH, N_, HD_, N_, 0, 0,
                            (long)N_*N_, (long)N_*HD_, (long)N_*HD_);

    // 6) rect projection + residual -> xx rows 1..196
    gemm_tf32<<<gx, 256>>>(rectH, Wr_proj, br_proj, x, xx, B_*N_, C_, C_, 0, 2, 0,0,0);

    // 7) MLP
    ln_kernel<<<B_*T_, 128>>>(xx, hdn, g3, b3, B_*T_, B_*T_, 0, C_);
    dim3 gm1(24, 25), gm2(6, 25);
    gemm_tf32<<<gm1, 256>>>(hdn, W1, bm1, nullptr, h1, B_*T_, 4*C_, C_, 1, 0, 0,0,0);
    gemm_tf32<<<gm2, 256>>>(h1, W2, bm2, xx, outp, B_*T_, C_, 4*C_, 0, 0, 0,0,0);

    // 8) anchors pass-through
    int n4 = NC_*T_*C_/4;
    copy_kernel<<<(n4 + 255)/256, 256>>>(x + (long)16*T_*C_, outp + (long)16*T_*C_, n4);
}